// round 1
// baseline (speedup 1.0000x reference)
#include <cuda_runtime.h>

#define BATCH 8
#define DIM   256
#define HH    128
#define WW    128
#define PPAT  4
#define HEADS 8
#define HD    32
#define HP    32
#define WPg   32
#define NTOK  1024
#define MTOT  8192
#define CPB   512
#define TBL   3969   // 63*63

// ---------------- scratch (device globals; no allocation) ----------------
__device__ float g_tok[MTOT * DIM];        // [m, c]   8 MB
__device__ float g_qkv[MTOT * 3 * DIM];    // [m, 3C]  25 MB
__device__ float g_att[MTOT * DIM];        // [m, c]   8 MB
__device__ float g_zp [MTOT * DIM];        // [m, c]   8 MB
__device__ float g_table[HEADS * TBL];     // [h, e]   127 KB

// ---------------- RPE MLP table: relu(rel @ w1^T + b1) @ w2^T ----------------
__global__ void rpe_kernel(const float* __restrict__ w1, const float* __restrict__ b1,
                           const float* __restrict__ w2) {
    __shared__ float sh[CPB];
    int e   = blockIdx.x;
    int tid = threadIdx.x;
    float rh = (float)((e / 63) - 31) * (1.0f / 31.0f);
    float rw = (float)((e % 63) - 31) * (1.0f / 31.0f);
    float r  = rh * w1[tid * 2] + rw * w1[tid * 2 + 1] + b1[tid];
    sh[tid]  = fmaxf(r, 0.0f);
    __syncthreads();
    int wid = tid >> 5, lane = tid & 31;
    if (wid < HEADS) {
        float s = 0.0f;
        for (int t = lane; t < CPB; t += 32) s += sh[t] * w2[wid * CPB + t];
        #pragma unroll
        for (int off = 16; off; off >>= 1) s += __shfl_xor_sync(0xffffffffu, s, off);
        if (lane == 0) g_table[wid * TBL + e] = s;
    }
}

// ---------------- patch embed: C[m,o] = sum_k patch(x)[m,k] * w_embed[o,k] + b ----------------
// M=8192, N=256, K=4096 (k = c*16 + p*4 + q). c advances linearly with K-step.
__global__ void embed_kernel(const float* __restrict__ x, const float* __restrict__ w,
                             const float* __restrict__ bias) {
    __shared__ float As[16 * 65];
    __shared__ float Bs[16 * 65];
    int tid = threadIdx.x;
    int n0 = blockIdx.x * 64, m0 = blockIdx.y * 64;
    int tx = tid & 15, ty = tid >> 4;

    int abase[4], asoff[4], bgoff[4], bsoff[4];
    #pragma unroll
    for (int i = 0; i < 4; i++) {
        int e  = tid + i * 256;
        int kl = e & 15, ml = e >> 4;
        int m  = m0 + ml;
        int b  = m >> 10, rem = m & 1023, hp = rem >> 5, wp = rem & 31;
        int p  = kl >> 2, qq = kl & 3;
        abase[i] = ((b * DIM) * HH + hp * PPAT + p) * WW + wp * PPAT + qq;  // c=0 base
        asoff[i] = kl * 65 + ml;
        bgoff[i] = (n0 + ml) * 4096 + kl;
        bsoff[i] = kl * 65 + ml;
    }
    float acc[4][4] = {};
    for (int s = 0; s < 256; s++) {           // c = s
        __syncthreads();
        #pragma unroll
        for (int i = 0; i < 4; i++) {
            As[asoff[i]] = x[abase[i] + s * (HH * WW)];
            Bs[bsoff[i]] = w[bgoff[i] + s * 16];
        }
        __syncthreads();
        #pragma unroll
        for (int k = 0; k < 16; k++) {
            float a[4], bb[4];
            #pragma unroll
            for (int i = 0; i < 4; i++) a[i]  = As[k * 65 + ty * 4 + i];
            #pragma unroll
            for (int j = 0; j < 4; j++) bb[j] = Bs[k * 65 + tx * 4 + j];
            #pragma unroll
            for (int i = 0; i < 4; i++)
                #pragma unroll
                for (int j = 0; j < 4; j++) acc[i][j] += a[i] * bb[j];
        }
    }
    #pragma unroll
    for (int i = 0; i < 4; i++) {
        int m = m0 + ty * 4 + i;
        #pragma unroll
        for (int j = 0; j < 4; j++) {
            int o = n0 + tx * 4 + j;
            g_tok[m * DIM + o] = acc[i][j] + bias[o];
        }
    }
}

// ---------------- generic C = A[M,256] * B[N,256]^T + bias  (qkv / proj) ----------------
__global__ void gemm_at_kernel(const float* __restrict__ Bm, const float* __restrict__ bias,
                               int which, int Nn) {
    const float* A = which ? g_att : g_tok;
    float*       C = which ? g_zp  : g_qkv;
    __shared__ float As[16 * 65];
    __shared__ float Bs[16 * 65];
    int tid = threadIdx.x;
    int n0 = blockIdx.x * 64, m0 = blockIdx.y * 64;
    int tx = tid & 15, ty = tid >> 4;
    float acc[4][4] = {};
    for (int s = 0; s < 16; s++) {            // K = 256
        __syncthreads();
        #pragma unroll
        for (int i = 0; i < 4; i++) {
            int e = tid + i * 256;
            int kl = e & 15, ml = e >> 4;
            As[kl * 65 + ml] = A [(m0 + ml) * 256 + s * 16 + kl];
            Bs[kl * 65 + ml] = Bm[(n0 + ml) * 256 + s * 16 + kl];
        }
        __syncthreads();
        #pragma unroll
        for (int k = 0; k < 16; k++) {
            float a[4], bb[4];
            #pragma unroll
            for (int i = 0; i < 4; i++) a[i]  = As[k * 65 + ty * 4 + i];
            #pragma unroll
            for (int j = 0; j < 4; j++) bb[j] = Bs[k * 65 + tx * 4 + j];
            #pragma unroll
            for (int i = 0; i < 4; i++)
                #pragma unroll
                for (int j = 0; j < 4; j++) acc[i][j] += a[i] * bb[j];
        }
    }
    #pragma unroll
    for (int i = 0; i < 4; i++) {
        int m = m0 + ty * 4 + i;
        #pragma unroll
        for (int j = 0; j < 4; j++) {
            int n = n0 + tx * 4 + j;
            C[m * Nn + n] = acc[i][j] + bias[n];
        }
    }
}

// ---------------- flash attention, warp per query row ----------------
__global__ void attn_kernel() {
    __shared__ float Ks[64 * 33];
    __shared__ float Vs[64 * 33];
    __shared__ float Ts[TBL];
    int tid = threadIdx.x;
    int bx = blockIdx.x;
    int rb = bx & 127, bh = bx >> 7;
    int b = bh >> 3, h = bh & 7;
    int wid = tid >> 5, lane = tid & 31;
    int n = rb * 8 + wid;

    for (int i = tid; i < TBL; i += 256) Ts[i] = g_table[h * TBL + i];

    const float* qp = &g_qkv[((b << 10) + n) * 768 + h * HD];
    float q[32];
    #pragma unroll
    for (int d = 0; d < 32; d++) q[d] = qp[d] * 0.17677669529663687f;  // 32^-0.5

    int iq = n >> 5, jq = n & 31;
    float run_max = -1e30f, lane_sum = 0.0f, acc = 0.0f;

    for (int t = 0; t < 16; t++) {
        int m0 = t * 64;
        __syncthreads();
        #pragma unroll
        for (int r = 0; r < 8; r++) {
            int row = r * 8 + wid;
            const float* kvp = &g_qkv[((b << 10) + (m0 + row)) * 768 + h * HD];
            Ks[row * 33 + lane] = kvp[256 + lane];
            Vs[row * 33 + lane] = kvp[512 + lane];
        }
        __syncthreads();

        int ma = m0 + lane, mb = ma + 32;
        float s0 = 0.0f, s1 = 0.0f;
        #pragma unroll
        for (int d = 0; d < 32; d++) {
            s0 += q[d] * Ks[lane * 33 + d];
            s1 += q[d] * Ks[(32 + lane) * 33 + d];
        }
        {
            int ka = ma >> 5, la = ma & 31;
            s0 += Ts[(iq - ka + 31) * 63 + (jq - la + 31)];
            int kb = mb >> 5, lb = mb & 31;
            s1 += Ts[(iq - kb + 31) * 63 + (jq - lb + 31)];
        }
        float tmax = fmaxf(s0, s1);
        #pragma unroll
        for (int off = 16; off; off >>= 1)
            tmax = fmaxf(tmax, __shfl_xor_sync(0xffffffffu, tmax, off));
        float new_max = fmaxf(run_max, tmax);
        float scl = __expf(run_max - new_max);
        float p0 = __expf(s0 - new_max);
        float p1 = __expf(s1 - new_max);
        lane_sum = lane_sum * scl + p0 + p1;
        acc *= scl;
        #pragma unroll
        for (int j2 = 0; j2 < 32; j2++) {
            float pp0 = __shfl_sync(0xffffffffu, p0, j2);
            float pp1 = __shfl_sync(0xffffffffu, p1, j2);
            acc += pp0 * Vs[j2 * 33 + lane] + pp1 * Vs[(32 + j2) * 33 + lane];
        }
        run_max = new_max;
    }
    float tot = lane_sum;
    #pragma unroll
    for (int off = 16; off; off >>= 1) tot += __shfl_xor_sync(0xffffffffu, tot, off);
    g_att[((b << 10) + n) * DIM + h * HD + lane] = acc * (1.0f / tot);
}

// ---------------- unembed: C = g_zp[8192,256] * w[256,4096], scatter to y ----------------
__global__ void unembed_kernel(const float* __restrict__ w, const float* __restrict__ bias,
                               float* __restrict__ y) {
    __shared__ float As[16 * 65];
    __shared__ float Bs[16 * 65];
    int tid = threadIdx.x;
    int n0 = blockIdx.x * 64, m0 = blockIdx.y * 64;
    int tx = tid & 15, ty = tid >> 4;
    float acc[4][4] = {};
    for (int s = 0; s < 16; s++) {            // K = 256
        __syncthreads();
        #pragma unroll
        for (int i = 0; i < 4; i++) {
            int e = tid + i * 256;
            { int kl = e & 15, ml = e >> 4;
              As[kl * 65 + ml] = g_zp[(m0 + ml) * 256 + s * 16 + kl]; }
            { int nl = e & 63, kl = e >> 6;
              Bs[kl * 65 + nl] = w[(s * 16 + kl) * 4096 + n0 + nl]; }
        }
        __syncthreads();
        #pragma unroll
        for (int k = 0; k < 16; k++) {
            float a[4], bb[4];
            #pragma unroll
            for (int i = 0; i < 4; i++) a[i]  = As[k * 65 + ty * 4 + i];
            #pragma unroll
            for (int j = 0; j < 4; j++) bb[j] = Bs[k * 65 + tx * 4 + j];
            #pragma unroll
            for (int i = 0; i < 4; i++)
                #pragma unroll
                for (int j = 0; j < 4; j++) acc[i][j] += a[i] * bb[j];
        }
    }
    #pragma unroll
    for (int i = 0; i < 4; i++) {
        int m = m0 + ty * 4 + i;
        int b = m >> 10, rem = m & 1023, hp = rem >> 5, wp = rem & 31;
        #pragma unroll
        for (int j = 0; j < 4; j++) {
            int np = n0 + tx * 4 + j;
            int o = np >> 4, p = (np >> 2) & 3, qq = np & 3;
            y[((b * DIM + o) * HH + hp * PPAT + p) * WW + wp * PPAT + qq]
                = acc[i][j] + bias[o];
        }
    }
}

// ---------------- launch ----------------
extern "C" void kernel_launch(void* const* d_in, const int* in_sizes, int n_in,
                              void* d_out, int out_size) {
    const float* x         = (const float*)d_in[0];
    const float* w_embed   = (const float*)d_in[1];
    const float* b_embed   = (const float*)d_in[2];
    const float* cpb_w1    = (const float*)d_in[3];
    const float* cpb_b1    = (const float*)d_in[4];
    const float* cpb_w2    = (const float*)d_in[5];
    const float* w_qkv     = (const float*)d_in[6];
    const float* b_qkv     = (const float*)d_in[7];
    const float* w_proj    = (const float*)d_in[8];
    const float* b_proj    = (const float*)d_in[9];
    const float* w_unembed = (const float*)d_in[10];
    const float* b_unembed = (const float*)d_in[11];
    float* y = (float*)d_out;

    rpe_kernel   <<<TBL, CPB>>>(cpb_w1, cpb_b1, cpb_w2);
    embed_kernel <<<dim3(4, 128), 256>>>(x, w_embed, b_embed);
    gemm_at_kernel<<<dim3(12, 128), 256>>>(w_qkv, b_qkv, /*which=*/0, 768);   // qkv
    attn_kernel  <<<8192, 256>>>();
    gemm_at_kernel<<<dim3(4, 128), 256>>>(w_proj, b_proj, /*which=*/1, 256);  // proj
    unembed_kernel<<<dim3(64, 128), 256>>>(w_unembed, b_unembed, y);
}

// round 2
// speedup vs baseline: 3.5689x; 3.5689x over previous
#include <cuda_runtime.h>

#define BATCH 8
#define DIM   256
#define HH    128
#define WW    128
#define HEADS 8
#define HD    32
#define MTOT  8192
#define CPB   512
#define TBL   3969   // 63*63

// ---------------- scratch (device globals; no allocation) ----------------
__device__ float g_tok[MTOT * DIM];        // [m, c]
__device__ float g_qkv[MTOT * 3 * DIM];    // [m, 3C]
__device__ float g_att[MTOT * DIM];        // [m, c]
__device__ float g_zp [MTOT * DIM];        // [m, c]
__device__ float g_table[HEADS * TBL];     // [h, e]

// ---------------- RPE MLP table ----------------
__global__ void rpe_kernel(const float* __restrict__ w1, const float* __restrict__ b1,
                           const float* __restrict__ w2) {
    __shared__ float sh[CPB];
    int e   = blockIdx.x;
    int tid = threadIdx.x;
    float rh = (float)((e / 63) - 31) * (1.0f / 31.0f);
    float rw = (float)((e % 63) - 31) * (1.0f / 31.0f);
    float r  = rh * w1[tid * 2] + rw * w1[tid * 2 + 1] + b1[tid];
    sh[tid]  = fmaxf(r, 0.0f);
    __syncthreads();
    int wid = tid >> 5, lane = tid & 31;
    if (wid < HEADS) {
        float s = 0.0f;
        for (int t = lane; t < CPB; t += 32) s += sh[t] * w2[wid * CPB + t];
        #pragma unroll
        for (int off = 16; off; off >>= 1) s += __shfl_xor_sync(0xffffffffu, s, off);
        if (lane == 0) g_table[wid * TBL + e] = s;
    }
}

// =======================================================================
// 128x128x8 SGEMM macro body: inner product + epilogue helpers
// =======================================================================
#define GEMM_INNER()                                                          \
    _Pragma("unroll")                                                         \
    for (int k = 0; k < 8; k++) {                                             \
        float4 a0 = *(const float4*)&As[k * 132 + ty * 4];                    \
        float4 a1 = *(const float4*)&As[k * 132 + 64 + ty * 4];               \
        float4 b0 = *(const float4*)&Bs[k * 132 + tx * 4];                    \
        float4 b1 = *(const float4*)&Bs[k * 132 + 64 + tx * 4];               \
        float ar[8] = {a0.x,a0.y,a0.z,a0.w,a1.x,a1.y,a1.z,a1.w};              \
        float br[8] = {b0.x,b0.y,b0.z,b0.w,b1.x,b1.y,b1.z,b1.w};              \
        _Pragma("unroll")                                                     \
        for (int i = 0; i < 8; i++)                                           \
            _Pragma("unroll")                                                 \
            for (int j = 0; j < 8; j++) acc[i][j] += ar[i] * br[j];           \
    }

#define GEMM_STORE_AB()                                                       \
    As[(akq + 0) * 132 + arow] = av.x;                                        \
    As[(akq + 1) * 132 + arow] = av.y;                                        \
    As[(akq + 2) * 132 + arow] = av.z;                                        \
    As[(akq + 3) * 132 + arow] = av.w;                                        \
    Bs[(akq + 0) * 132 + arow] = bv.x;                                        \
    Bs[(akq + 1) * 132 + arow] = bv.y;                                        \
    Bs[(akq + 2) * 132 + arow] = bv.z;                                        \
    Bs[(akq + 3) * 132 + arow] = bv.w;

// ---------------- generic C = A[M,256] * B[N,256]^T + bias  (qkv / proj) ----
__global__ __launch_bounds__(256, 2)
void gemm_nt_kernel(const float* __restrict__ Bm, const float* __restrict__ bias,
                    int which, int Nn) {
    const float* A = which ? g_att : g_tok;
    float*       C = which ? g_zp  : g_qkv;
    __shared__ float As[8 * 132];
    __shared__ float Bs[8 * 132];
    int tid = threadIdx.x;
    int n0 = blockIdx.x * 128, m0 = blockIdx.y * 128;
    int tx = tid & 15, ty = tid >> 4;
    int arow = tid >> 1, akq = (tid & 1) * 4;

    const float* Ap = A  + (m0 + arow) * 256 + akq;
    const float* Bp = Bm + (n0 + arow) * 256 + akq;
    float acc[8][8] = {};
    float4 av = *(const float4*)(Ap);
    float4 bv = *(const float4*)(Bp);
    for (int s = 0; s < 32; s++) {
        __syncthreads();
        GEMM_STORE_AB();
        __syncthreads();
        if (s < 31) { av = *(const float4*)(Ap + (s + 1) * 8);
                      bv = *(const float4*)(Bp + (s + 1) * 8); }
        GEMM_INNER();
    }
    float bb[8];
    #pragma unroll
    for (int j = 0; j < 8; j++) bb[j] = bias[n0 + (j < 4 ? tx * 4 + j : 64 + tx * 4 + j - 4)];
    #pragma unroll
    for (int i = 0; i < 8; i++) {
        int r = m0 + (i < 4 ? ty * 4 + i : 64 + ty * 4 + i - 4);
        float4 c0 = {acc[i][0] + bb[0], acc[i][1] + bb[1], acc[i][2] + bb[2], acc[i][3] + bb[3]};
        float4 c1 = {acc[i][4] + bb[4], acc[i][5] + bb[5], acc[i][6] + bb[6], acc[i][7] + bb[7]};
        *(float4*)&C[r * Nn + n0 + tx * 4]      = c0;
        *(float4*)&C[r * Nn + n0 + 64 + tx * 4] = c1;
    }
}

// ---------------- patch embed: gathered A, K=4096 ----------------
__global__ __launch_bounds__(256, 2)
void embed_kernel(const float* __restrict__ x, const float* __restrict__ w,
                  const float* __restrict__ bias) {
    __shared__ float As[8 * 132];
    __shared__ float Bs[8 * 132];
    int tid = threadIdx.x;
    int n0 = blockIdx.x * 128, m0 = blockIdx.y * 128;
    int tx = tid & 15, ty = tid >> 4;
    int arow = tid >> 1, akq = (tid & 1) * 4;

    int m  = m0 + arow;
    int b  = m >> 10, hp = (m >> 5) & 31, wp = m & 31;
    long xb = (long)b * (256 * 16384) + hp * 512 + wp * 4;   // c=0, p=0 base
    const float* Bp = w + (n0 + arow) * 4096 + akq;

    float acc[8][8] = {};
    // s: chunk index, c = s>>1, p = ((s&1)*8 + akq) >> 2
    int c0 = 0, p0 = akq >> 2;
    float4 av = *(const float4*)(x + xb + p0 * 128);
    float4 bv = *(const float4*)(Bp);
    for (int s = 0; s < 512; s++) {
        __syncthreads();
        GEMM_STORE_AB();
        __syncthreads();
        if (s < 511) {
            int s1 = s + 1;
            int c  = s1 >> 1;
            int p  = (((s1 & 1) << 3) + akq) >> 2;
            av = *(const float4*)(x + xb + (long)c * 16384 + p * 128);
            bv = *(const float4*)(Bp + s1 * 8);
        }
        GEMM_INNER();
        (void)c0; (void)p0;
    }
    float bb[8];
    #pragma unroll
    for (int j = 0; j < 8; j++) bb[j] = bias[n0 + (j < 4 ? tx * 4 + j : 64 + tx * 4 + j - 4)];
    #pragma unroll
    for (int i = 0; i < 8; i++) {
        int r = m0 + (i < 4 ? ty * 4 + i : 64 + ty * 4 + i - 4);
        float4 cc0 = {acc[i][0] + bb[0], acc[i][1] + bb[1], acc[i][2] + bb[2], acc[i][3] + bb[3]};
        float4 cc1 = {acc[i][4] + bb[4], acc[i][5] + bb[5], acc[i][6] + bb[6], acc[i][7] + bb[7]};
        *(float4*)&g_tok[r * 256 + n0 + tx * 4]      = cc0;
        *(float4*)&g_tok[r * 256 + n0 + 64 + tx * 4] = cc1;
    }
}

// ---------------- unembed: C = g_zp[8192,256] * w[256,4096], scatter ----------
__global__ __launch_bounds__(256, 2)
void unembed_kernel(const float* __restrict__ w, const float* __restrict__ bias,
                    float* __restrict__ y) {
    __shared__ float As[8 * 132];
    __shared__ float Bs[8 * 132];
    int tid = threadIdx.x;
    int n0 = blockIdx.x * 128, m0 = blockIdx.y * 128;
    int tx = tid & 15, ty = tid >> 4;
    int arow = tid >> 1, akq = (tid & 1) * 4;
    int bkrow = tid >> 5, bn4 = (tid & 31) * 4;

    const float* Ap = g_zp + (m0 + arow) * 256 + akq;
    const float* Bp = w + bkrow * 4096 + n0 + bn4;
    float acc[8][8] = {};
    float4 av = *(const float4*)(Ap);
    float4 bv = *(const float4*)(Bp);
    for (int s = 0; s < 32; s++) {
        __syncthreads();
        As[(akq + 0) * 132 + arow] = av.x;
        As[(akq + 1) * 132 + arow] = av.y;
        As[(akq + 2) * 132 + arow] = av.z;
        As[(akq + 3) * 132 + arow] = av.w;
        *(float4*)&Bs[bkrow * 132 + bn4] = bv;
        __syncthreads();
        if (s < 31) { av = *(const float4*)(Ap + (s + 1) * 8);
                      bv = *(const float4*)(Bp + (s + 1) * 8 * 4096); }
        GEMM_INNER();
    }
    #pragma unroll
    for (int i = 0; i < 8; i++) {
        int r = m0 + (i < 4 ? ty * 4 + i : 64 + ty * 4 + i - 4);
        int b = r >> 10, hp = (r >> 5) & 31, wp = r & 31;
        #pragma unroll
        for (int half = 0; half < 2; half++) {
            int np0 = n0 + half * 64 + tx * 4;
            int o = np0 >> 4, p = (np0 >> 2) & 3;
            float bo = bias[o];
            float4 cc;
            cc.x = acc[i][half * 4 + 0] + bo;
            cc.y = acc[i][half * 4 + 1] + bo;
            cc.z = acc[i][half * 4 + 2] + bo;
            cc.w = acc[i][half * 4 + 3] + bo;
            *(float4*)&y[((long)(b * 256 + o) * 128 + hp * 4 + p) * 128 + wp * 4] = cc;
        }
    }
}

// ---------------- GEMM-style flash attention: 64 queries/block ----------------
__global__ __launch_bounds__(256, 2)
void attn_kernel() {
    __shared__ float Qt[32 * 68];   // [d][q]
    __shared__ float Kt[32 * 68];   // [d][k]
    __shared__ float Vs[64 * 36];   // [k][d]
    __shared__ float Ps[64 * 68];   // [q][k]
    int tid = threadIdx.x;
    int bx = blockIdx.x;
    int qb = bx & 15, bh = bx >> 4;
    int b = bh >> 3, h = bh & 7;
    int n0 = qb * 64;
    int tx = tid & 15, ty = tid >> 4;

    // load + scale Q (transposed)
    #pragma unroll
    for (int r = 0; r < 8; r++) {
        int idx = tid + r * 256;
        int q = idx >> 5, d = idx & 31;
        Qt[d * 68 + q] = g_qkv[((b << 10) + n0 + q) * 768 + h * 32 + d]
                         * 0.17677669529663687f;
    }

    int base_i[4];
    #pragma unroll
    for (int i = 0; i < 4; i++) {
        int n = n0 + 4 * ty + i;
        base_i[i] = ((n >> 5) + 31) * 63 + (n & 31) + 31;
    }
    const float* tab = g_table + h * TBL;

    float mold[4], l[4], O[4][2];
    #pragma unroll
    for (int i = 0; i < 4; i++) { mold[i] = -1e30f; l[i] = 0.0f; O[i][0] = 0.0f; O[i][1] = 0.0f; }

    int krow = tid >> 2;            // 0..63
    int dg   = (tid & 3) * 4;       // 0,4,8,12

    for (int t = 0; t < 16; t++) {
        int m0 = t * 64;
        __syncthreads();
        {
            const float* kv = g_qkv + ((b << 10) + m0 + krow) * 768 + h * 32;
            float4 k0 = *(const float4*)(kv + 256 + dg);
            float4 k1 = *(const float4*)(kv + 256 + dg + 16);
            float4 v0 = *(const float4*)(kv + 512 + dg);
            float4 v1 = *(const float4*)(kv + 512 + dg + 16);
            Kt[(dg + 0) * 68 + krow] = k0.x; Kt[(dg + 1) * 68 + krow] = k0.y;
            Kt[(dg + 2) * 68 + krow] = k0.z; Kt[(dg + 3) * 68 + krow] = k0.w;
            Kt[(dg + 16) * 68 + krow] = k1.x; Kt[(dg + 17) * 68 + krow] = k1.y;
            Kt[(dg + 18) * 68 + krow] = k1.z; Kt[(dg + 19) * 68 + krow] = k1.w;
            *(float4*)&Vs[krow * 36 + dg]      = v0;
            *(float4*)&Vs[krow * 36 + dg + 16] = v1;
        }
        __syncthreads();

        // S = Qt^T * Kt  (4x4 per thread)
        float acc[4][4] = {};
        #pragma unroll
        for (int d = 0; d < 32; d++) {
            float4 aq = *(const float4*)&Qt[d * 68 + ty * 4];
            float4 bk = *(const float4*)&Kt[d * 68 + tx * 4];
            float aa[4] = {aq.x, aq.y, aq.z, aq.w};
            float kk[4] = {bk.x, bk.y, bk.z, bk.w};
            #pragma unroll
            for (int i = 0; i < 4; i++)
                #pragma unroll
                for (int j = 0; j < 4; j++) acc[i][j] += aa[i] * kk[j];
        }
        // + bias
        int moff[4];
        #pragma unroll
        for (int j = 0; j < 4; j++) {
            int m = m0 + 4 * tx + j;
            moff[j] = (m >> 5) * 63 + (m & 31);
        }
        #pragma unroll
        for (int i = 0; i < 4; i++)
            #pragma unroll
            for (int j = 0; j < 4; j++)
                acc[i][j] += __ldg(&tab[base_i[i] - moff[j]]);

        // online softmax, row stats across tx (16-lane group)
        #pragma unroll
        for (int i = 0; i < 4; i++) {
            float rm = fmaxf(fmaxf(acc[i][0], acc[i][1]), fmaxf(acc[i][2], acc[i][3]));
            #pragma unroll
            for (int off = 1; off < 16; off <<= 1)
                rm = fmaxf(rm, __shfl_xor_sync(0xffffffffu, rm, off));
            float mnew = fmaxf(mold[i], rm);
            float scl  = __expf(mold[i] - mnew);
            float p0 = __expf(acc[i][0] - mnew);
            float p1 = __expf(acc[i][1] - mnew);
            float p2 = __expf(acc[i][2] - mnew);
            float p3 = __expf(acc[i][3] - mnew);
            float ps = p0 + p1 + p2 + p3;
            #pragma unroll
            for (int off = 1; off < 16; off <<= 1)
                ps += __shfl_xor_sync(0xffffffffu, ps, off);
            l[i] = l[i] * scl + ps;
            O[i][0] *= scl; O[i][1] *= scl;
            mold[i] = mnew;
            float4 pv = {p0, p1, p2, p3};
            *(float4*)&Ps[(4 * ty + i) * 68 + tx * 4] = pv;
        }
        __syncwarp();

        // O += P * V  (4q x 2d per thread, d = 2*tx..2*tx+1)
        #pragma unroll
        for (int k0 = 0; k0 < 64; k0 += 4) {
            float4 pa[4];
            #pragma unroll
            for (int i = 0; i < 4; i++)
                pa[i] = *(const float4*)&Ps[(4 * ty + i) * 68 + k0];
            #pragma unroll
            for (int kk = 0; kk < 4; kk++) {
                float2 v = *(const float2*)&Vs[(k0 + kk) * 36 + 2 * tx];
                float pr[4] = {((float*)&pa[0])[kk], ((float*)&pa[1])[kk],
                               ((float*)&pa[2])[kk], ((float*)&pa[3])[kk]};
                #pragma unroll
                for (int i = 0; i < 4; i++) {
                    O[i][0] += pr[i] * v.x;
                    O[i][1] += pr[i] * v.y;
                }
            }
        }
        __syncwarp();
    }

    #pragma unroll
    for (int i = 0; i < 4; i++) {
        float inv = 1.0f / l[i];
        int n = n0 + 4 * ty + i;
        float2 o = {O[i][0] * inv, O[i][1] * inv};
        *(float2*)&g_att[((b << 10) + n) * 256 + h * 32 + 2 * tx] = o;
    }
}

// ---------------- launch ----------------
extern "C" void kernel_launch(void* const* d_in, const int* in_sizes, int n_in,
                              void* d_out, int out_size) {
    const float* x         = (const float*)d_in[0];
    const float* w_embed   = (const float*)d_in[1];
    const float* b_embed   = (const float*)d_in[2];
    const float* cpb_w1    = (const float*)d_in[3];
    const float* cpb_b1    = (const float*)d_in[4];
    const float* cpb_w2    = (const float*)d_in[5];
    const float* w_qkv     = (const float*)d_in[6];
    const float* b_qkv     = (const float*)d_in[7];
    const float* w_proj    = (const float*)d_in[8];
    const float* b_proj    = (const float*)d_in[9];
    const float* w_unembed = (const float*)d_in[10];
    const float* b_unembed = (const float*)d_in[11];
    float* y = (float*)d_out;

    rpe_kernel    <<<TBL, CPB>>>(cpb_w1, cpb_b1, cpb_w2);
    embed_kernel  <<<dim3(2, 64), 256>>>(x, w_embed, b_embed);
    gemm_nt_kernel<<<dim3(6, 64), 256>>>(w_qkv, b_qkv, /*which=*/0, 768);
    attn_kernel   <<<1024, 256>>>();
    gemm_nt_kernel<<<dim3(2, 64), 256>>>(w_proj, b_proj, /*which=*/1, 256);
    unembed_kernel<<<dim3(32, 64), 256>>>(w_unembed, b_unembed, y);
}

// round 4
// speedup vs baseline: 4.9457x; 1.3858x over previous
#include <cuda_runtime.h>
#include <cuda_bf16.h>
#include <stdint.h>

#define HEADS 8
#define MTOT  8192
#define CPB   512
#define TBL   3969   // 63*63

// ---------------- scratch (device globals; no allocation) ----------------
__device__ float g_tok[MTOT * 256];
__device__ float g_qkv[MTOT * 768];
__device__ float g_att[MTOT * 256];
__device__ float g_zp [MTOT * 256];
__device__ float g_wt [4096 * 256];     // unembed weight transposed [n'][c]
__device__ float g_table[HEADS * TBL];

// ================= helpers =================
__device__ __forceinline__ uint32_t smem_u32(const void* p) {
    uint32_t a;
    asm("{ .reg .u64 t; cvta.to.shared.u64 t, %1; cvt.u32.u64 %0, t; }" : "=r"(a) : "l"(p));
    return a;
}
__device__ __forceinline__ void ldsm4(uint32_t* r, uint32_t addr) {
    asm volatile("ldmatrix.sync.aligned.m8n8.x4.shared.b16 {%0,%1,%2,%3}, [%4];"
        : "=r"(r[0]), "=r"(r[1]), "=r"(r[2]), "=r"(r[3]) : "r"(addr));
}
__device__ __forceinline__ void mma16816(float* d, const uint32_t* a, const uint32_t* b) {
    asm volatile("mma.sync.aligned.m16n8k16.row.col.f32.bf16.bf16.f32 "
        "{%0,%1,%2,%3}, {%4,%5,%6,%7}, {%8,%9}, {%0,%1,%2,%3};"
        : "+f"(d[0]), "+f"(d[1]), "+f"(d[2]), "+f"(d[3])
        : "r"(a[0]), "r"(a[1]), "r"(a[2]), "r"(a[3]), "r"(b[0]), "r"(b[1]));
}
__device__ __forceinline__ uint32_t packbf(__nv_bfloat16 a, __nv_bfloat16 b) {
    __nv_bfloat162 t = __halves2bfloat162(a, b);
    return *(uint32_t*)&t;
}
// split 8 floats -> 4 packed hi words + 4 packed lo words, store 16B each
__device__ __forceinline__ void cvt_store8(uint16_t* hiA, uint16_t* loA, int off,
                                           float4 v0, float4 v1) {
    float f[8] = {v0.x, v0.y, v0.z, v0.w, v1.x, v1.y, v1.z, v1.w};
    uint32_t h[4], l[4];
    #pragma unroll
    for (int i = 0; i < 4; i++) {
        __nv_bfloat16 h0 = __float2bfloat16_rn(f[2 * i]);
        __nv_bfloat16 h1 = __float2bfloat16_rn(f[2 * i + 1]);
        float r0 = f[2 * i]     - __bfloat162float(h0);
        float r1 = f[2 * i + 1] - __bfloat162float(h1);
        h[i] = packbf(h0, h1);
        l[i] = packbf(__float2bfloat16_rn(r0), __float2bfloat16_rn(r1));
    }
    *(uint4*)&hiA[off] = *(uint4*)h;
    *(uint4*)&loA[off] = *(uint4*)l;
}

// ---------------- RPE MLP table ----------------
__global__ void rpe_kernel(const float* __restrict__ w1, const float* __restrict__ b1,
                           const float* __restrict__ w2) {
    __shared__ float sh[CPB];
    int e   = blockIdx.x;
    int tid = threadIdx.x;
    float rh = (float)((e / 63) - 31) * (1.0f / 31.0f);
    float rw = (float)((e % 63) - 31) * (1.0f / 31.0f);
    float r  = rh * w1[tid * 2] + rw * w1[tid * 2 + 1] + b1[tid];
    sh[tid]  = fmaxf(r, 0.0f);
    __syncthreads();
    int wid = tid >> 5, lane = tid & 31;
    if (wid < HEADS) {
        float s = 0.0f;
        for (int t = lane; t < CPB; t += 32) s += sh[t] * w2[wid * CPB + t];
        #pragma unroll
        for (int off = 16; off; off >>= 1) s += __shfl_xor_sync(0xffffffffu, s, off);
        if (lane == 0) g_table[wid * TBL + e] = s;
    }
}

// ---------------- transpose unembed weight: g_wt[n'][c] = w[c][n'] ----------------
__global__ void wt_kernel(const float* __restrict__ w) {
    __shared__ float t[32][33];
    int n0 = blockIdx.x * 32, c0 = blockIdx.y * 32;
    int tx = threadIdx.x, ty = threadIdx.y;
    #pragma unroll
    for (int r = 0; r < 4; r++)
        t[ty + 8 * r][tx] = w[(c0 + ty + 8 * r) * 4096 + n0 + tx];
    __syncthreads();
    #pragma unroll
    for (int r = 0; r < 4; r++)
        g_wt[(n0 + ty + 8 * r) * 256 + c0 + tx] = t[tx][ty + 8 * r];
}

// ================= bf16x3 tensor-core GEMM (mma.sync, base-arch PTX) =================
// C[M=8192, N] = A[M,K] * B[N,K]^T + bias,  A,B fp32 -> (hi,lo) bf16 split, 3 products
// asel: 0 = gather patches from x (embed), 1 = g_tok, 2 = g_att, 3 = g_zp
// csel: 0 -> g_tok, 1 -> g_qkv (ldc 768), 2 -> g_zp, 3 -> ConvTranspose scatter to y
#define SROW 40   // bf16 elements per smem row (16 data + pad); 80B stride
__global__ __launch_bounds__(256, 2)
void mma_gemm(const float* __restrict__ Ag, const float* __restrict__ Bext,
              const float* __restrict__ bias, float* __restrict__ yout,
              int asel, int csel, int K) {
    __shared__ __align__(16) uint16_t sAhi[128 * SROW];
    __shared__ __align__(16) uint16_t sAlo[128 * SROW];
    __shared__ __align__(16) uint16_t sBhi[128 * SROW];
    __shared__ __align__(16) uint16_t sBlo[128 * SROW];

    int tid = threadIdx.x, wid = tid >> 5, lane = tid & 31;
    int n0 = blockIdx.x * 128, m0 = blockIdx.y * 128;

    const float* A = asel == 1 ? g_tok : asel == 2 ? g_att : g_zp;
    const float* B = Bext ? Bext : g_wt;

    // ---- load geometry: thread handles row lrow, k-half lkh (8 k's) ----
    int lrow = tid >> 1, lkh = (tid & 1) * 8;
    const float* aG;
    long astep; int a2;
    if (asel == 0) {
        int m = m0 + lrow;
        int b = m >> 10, hp = (m >> 5) & 31, wp = m & 31;
        int p = lkh >> 2;                     // 0 or 2
        aG = Ag + (long)b * (256 * 16384) + (hp * 4 + p) * 128 + wp * 4;
        astep = 16384; a2 = 128;              // next chunk = next channel; p+1 row
    } else {
        aG = A + (long)(m0 + lrow) * K + lkh;
        astep = 16; a2 = 4;
    }
    const float* bG = B + (long)(n0 + lrow) * K + lkh;
    int sOff = lrow * SROW + lkh;

    // ---- fragment smem addresses ----
    int wm = (wid >> 1) * 32, wn = (wid & 1) * 64;
    uint32_t baseAhi = smem_u32(sAhi), baseAlo = smem_u32(sAlo);
    uint32_t baseBhi = smem_u32(sBhi), baseBlo = smem_u32(sBlo);
    int arow = wm + (lane & 15), acol = (lane >> 4) * 8;
    uint32_t aHiAd0 = baseAhi + (arow * SROW + acol) * 2;
    uint32_t aHiAd1 = aHiAd0 + 16 * SROW * 2;
    uint32_t aLoAd0 = baseAlo + (arow * SROW + acol) * 2;
    uint32_t aLoAd1 = aLoAd0 + 16 * SROW * 2;
    int brow = wn + (lane & 7) + ((lane >> 4) << 3), bcol = lane & 8;
    uint32_t bHiAd[4], bLoAd[4];
    #pragma unroll
    for (int g = 0; g < 4; g++) {
        bHiAd[g] = baseBhi + ((brow + g * 16) * SROW + bcol) * 2;
        bLoAd[g] = baseBlo + ((brow + g * 16) * SROW + bcol) * 2;
    }

    float acc[2][8][4] = {};
    int nc = K / 16;
    float4 av0 = *(const float4*)(aG);
    float4 av1 = *(const float4*)(aG + a2);
    float4 bv0 = *(const float4*)(bG);
    float4 bv1 = *(const float4*)(bG + 4);

    for (int c = 0; c < nc; c++) {
        __syncthreads();
        cvt_store8(sAhi, sAlo, sOff, av0, av1);
        cvt_store8(sBhi, sBlo, sOff, bv0, bv1);
        __syncthreads();
        if (c + 1 < nc) {
            av0 = *(const float4*)(aG + (long)(c + 1) * astep);
            av1 = *(const float4*)(aG + (long)(c + 1) * astep + a2);
            bv0 = *(const float4*)(bG + (c + 1) * 16);
            bv1 = *(const float4*)(bG + (c + 1) * 16 + 4);
        }
        uint32_t ah[2][4], xf[2][4], bh[4][4];
        ldsm4(ah[0], aHiAd0); ldsm4(ah[1], aHiAd1);
        #pragma unroll
        for (int g = 0; g < 4; g++) ldsm4(bh[g], bHiAd[g]);
        // hi * hi
        #pragma unroll
        for (int mf = 0; mf < 2; mf++)
            #pragma unroll
            for (int g = 0; g < 4; g++) {
                mma16816(acc[mf][g * 2 + 0], ah[mf], &bh[g][0]);
                mma16816(acc[mf][g * 2 + 1], ah[mf], &bh[g][2]);
            }
        // lo * hi
        ldsm4(xf[0], aLoAd0); ldsm4(xf[1], aLoAd1);
        #pragma unroll
        for (int mf = 0; mf < 2; mf++)
            #pragma unroll
            for (int g = 0; g < 4; g++) {
                mma16816(acc[mf][g * 2 + 0], xf[mf], &bh[g][0]);
                mma16816(acc[mf][g * 2 + 1], xf[mf], &bh[g][2]);
            }
        // hi * lo
        #pragma unroll
        for (int g = 0; g < 4; g++) ldsm4(bh[g], bLoAd[g]);
        #pragma unroll
        for (int mf = 0; mf < 2; mf++)
            #pragma unroll
            for (int g = 0; g < 4; g++) {
                mma16816(acc[mf][g * 2 + 0], ah[mf], &bh[g][0]);
                mma16816(acc[mf][g * 2 + 1], ah[mf], &bh[g][2]);
            }
    }

    // ---- epilogue ----
    int r0 = m0 + wm + (lane >> 2);
    int nb = n0 + wn + (lane & 3) * 2;
    #pragma unroll
    for (int mf = 0; mf < 2; mf++) {
        int r = r0 + mf * 16;
        #pragma unroll
        for (int nf = 0; nf < 8; nf++) {
            int n = nb + nf * 8;
            float* d = acc[mf][nf];
            if (csel < 3) {
                float* C = csel == 0 ? g_tok : csel == 1 ? g_qkv : g_zp;
                int ldc = (csel == 1) ? 768 : 256;
                float b0 = __ldg(&bias[n]), b1 = __ldg(&bias[n + 1]);
                float2 lo2 = {d[0] + b0, d[1] + b1};
                float2 hi2 = {d[2] + b0, d[3] + b1};
                *(float2*)&C[(long)r * ldc + n]       = lo2;
                *(float2*)&C[(long)(r + 8) * ldc + n] = hi2;
            } else {
                int o = n >> 4, p = (n >> 2) & 3, q = n & 3;
                float bo = __ldg(&bias[o]);
                int b  = r >> 10, hp = (r >> 5) & 31, wp = r & 31;
                float2 lo2 = {d[0] + bo, d[1] + bo};
                *(float2*)&yout[((long)(b * 256 + o) * 128 + hp * 4 + p) * 128 + wp * 4 + q] = lo2;
                int r8 = r + 8;
                int b2 = r8 >> 10, hp2 = (r8 >> 5) & 31, wp2 = r8 & 31;
                float2 hi2 = {d[2] + bo, d[3] + bo};
                *(float2*)&yout[((long)(b2 * 256 + o) * 128 + hp2 * 4 + p) * 128 + wp2 * 4 + q] = hi2;
            }
        }
    }
}

// ---------------- GEMM-style flash attention (R2, unchanged) ----------------
__global__ __launch_bounds__(256, 2)
void attn_kernel() {
    __shared__ float Qt[32 * 68];
    __shared__ float Kt[32 * 68];
    __shared__ float Vs[64 * 36];
    __shared__ float Ps[64 * 68];
    int tid = threadIdx.x;
    int bx = blockIdx.x;
    int qb = bx & 15, bh = bx >> 4;
    int b = bh >> 3, h = bh & 7;
    int n0 = qb * 64;
    int tx = tid & 15, ty = tid >> 4;

    #pragma unroll
    for (int r = 0; r < 8; r++) {
        int idx = tid + r * 256;
        int q = idx >> 5, d = idx & 31;
        Qt[d * 68 + q] = g_qkv[((b << 10) + n0 + q) * 768 + h * 32 + d]
                         * 0.17677669529663687f;
    }
    int base_i[4];
    #pragma unroll
    for (int i = 0; i < 4; i++) {
        int n = n0 + 4 * ty + i;
        base_i[i] = ((n >> 5) + 31) * 63 + (n & 31) + 31;
    }
    const float* tab = g_table + h * TBL;

    float mold[4], l[4], O[4][2];
    #pragma unroll
    for (int i = 0; i < 4; i++) { mold[i] = -1e30f; l[i] = 0.0f; O[i][0] = 0.0f; O[i][1] = 0.0f; }

    int krow = tid >> 2;
    int dg   = (tid & 3) * 4;

    for (int t = 0; t < 16; t++) {
        int m0 = t * 64;
        __syncthreads();
        {
            const float* kv = g_qkv + ((b << 10) + m0 + krow) * 768 + h * 32;
            float4 k0 = *(const float4*)(kv + 256 + dg);
            float4 k1 = *(const float4*)(kv + 256 + dg + 16);
            float4 v0 = *(const float4*)(kv + 512 + dg);
            float4 v1 = *(const float4*)(kv + 512 + dg + 16);
            Kt[(dg + 0) * 68 + krow] = k0.x; Kt[(dg + 1) * 68 + krow] = k0.y;
            Kt[(dg + 2) * 68 + krow] = k0.z; Kt[(dg + 3) * 68 + krow] = k0.w;
            Kt[(dg + 16) * 68 + krow] = k1.x; Kt[(dg + 17) * 68 + krow] = k1.y;
            Kt[(dg + 18) * 68 + krow] = k1.z; Kt[(dg + 19) * 68 + krow] = k1.w;
            *(float4*)&Vs[krow * 36 + dg]      = v0;
            *(float4*)&Vs[krow * 36 + dg + 16] = v1;
        }
        __syncthreads();

        float acc[4][4] = {};
        #pragma unroll
        for (int d = 0; d < 32; d++) {
            float4 aq = *(const float4*)&Qt[d * 68 + ty * 4];
            float4 bk = *(const float4*)&Kt[d * 68 + tx * 4];
            float aa[4] = {aq.x, aq.y, aq.z, aq.w};
            float kk[4] = {bk.x, bk.y, bk.z, bk.w};
            #pragma unroll
            for (int i = 0; i < 4; i++)
                #pragma unroll
                for (int j = 0; j < 4; j++) acc[i][j] += aa[i] * kk[j];
        }
        int moff[4];
        #pragma unroll
        for (int j = 0; j < 4; j++) {
            int m = m0 + 4 * tx + j;
            moff[j] = (m >> 5) * 63 + (m & 31);
        }
        #pragma unroll
        for (int i = 0; i < 4; i++)
            #pragma unroll
            for (int j = 0; j < 4; j++)
                acc[i][j] += __ldg(&tab[base_i[i] - moff[j]]);

        #pragma unroll
        for (int i = 0; i < 4; i++) {
            float rm = fmaxf(fmaxf(acc[i][0], acc[i][1]), fmaxf(acc[i][2], acc[i][3]));
            #pragma unroll
            for (int off = 1; off < 16; off <<= 1)
                rm = fmaxf(rm, __shfl_xor_sync(0xffffffffu, rm, off));
            float mnew = fmaxf(mold[i], rm);
            float scl  = __expf(mold[i] - mnew);
            float p0 = __expf(acc[i][0] - mnew);
            float p1 = __expf(acc[i][1] - mnew);
            float p2 = __expf(acc[i][2] - mnew);
            float p3 = __expf(acc[i][3] - mnew);
            float ps = p0 + p1 + p2 + p3;
            #pragma unroll
            for (int off = 1; off < 16; off <<= 1)
                ps += __shfl_xor_sync(0xffffffffu, ps, off);
            l[i] = l[i] * scl + ps;
            O[i][0] *= scl; O[i][1] *= scl;
            mold[i] = mnew;
            float4 pv = {p0, p1, p2, p3};
            *(float4*)&Ps[(4 * ty + i) * 68 + tx * 4] = pv;
        }
        __syncwarp();

        #pragma unroll
        for (int k0 = 0; k0 < 64; k0 += 4) {
            float4 pa[4];
            #pragma unroll
            for (int i = 0; i < 4; i++)
                pa[i] = *(const float4*)&Ps[(4 * ty + i) * 68 + k0];
            #pragma unroll
            for (int kk = 0; kk < 4; kk++) {
                float2 v = *(const float2*)&Vs[(k0 + kk) * 36 + 2 * tx];
                float pr[4] = {((float*)&pa[0])[kk], ((float*)&pa[1])[kk],
                               ((float*)&pa[2])[kk], ((float*)&pa[3])[kk]};
                #pragma unroll
                for (int i = 0; i < 4; i++) {
                    O[i][0] += pr[i] * v.x;
                    O[i][1] += pr[i] * v.y;
                }
            }
        }
        __syncwarp();
    }

    #pragma unroll
    for (int i = 0; i < 4; i++) {
        float inv = 1.0f / l[i];
        int n = n0 + 4 * ty + i;
        float2 o = {O[i][0] * inv, O[i][1] * inv};
        *(float2*)&g_att[((b << 10) + n) * 256 + h * 32 + 2 * tx] = o;
    }
}

// ---------------- launch ----------------
extern "C" void kernel_launch(void* const* d_in, const int* in_sizes, int n_in,
                              void* d_out, int out_size) {
    const float* x         = (const float*)d_in[0];
    const float* w_embed   = (const float*)d_in[1];
    const float* b_embed   = (const float*)d_in[2];
    const float* cpb_w1    = (const float*)d_in[3];
    const float* cpb_b1    = (const float*)d_in[4];
    const float* cpb_w2    = (const float*)d_in[5];
    const float* w_qkv     = (const float*)d_in[6];
    const float* b_qkv     = (const float*)d_in[7];
    const float* w_proj    = (const float*)d_in[8];
    const float* b_proj    = (const float*)d_in[9];
    const float* w_unembed = (const float*)d_in[10];
    const float* b_unembed = (const float*)d_in[11];
    float* y = (float*)d_out;

    rpe_kernel<<<TBL, CPB>>>(cpb_w1, cpb_b1, cpb_w2);
    wt_kernel <<<dim3(128, 8), dim3(32, 8)>>>(w_unembed);
    // embed: gather x patches, B=w_embed [256x4096], K=4096 -> g_tok
    mma_gemm<<<dim3(2, 64), 256>>>(x, w_embed, b_embed, nullptr, 0, 0, 4096);
    // qkv: A=g_tok, B=w_qkv [768x256], K=256 -> g_qkv
    mma_gemm<<<dim3(6, 64), 256>>>(nullptr, w_qkv, b_qkv, nullptr, 1, 1, 256);
    attn_kernel<<<1024, 256>>>();
    // proj: A=g_att, B=w_proj [256x256], K=256 -> g_zp
    mma_gemm<<<dim3(2, 64), 256>>>(nullptr, w_proj, b_proj, nullptr, 2, 2, 256);
    // unembed: A=g_zp, B=g_wt [4096x256], K=256 -> scatter y
    mma_gemm<<<dim3(32, 64), 256>>>(nullptr, nullptr, b_unembed, y, 3, 3, 256);
}

// round 6
// speedup vs baseline: 6.2962x; 1.2731x over previous
#include <cuda_runtime.h>
#include <cuda_bf16.h>
#include <stdint.h>

#define HEADS 8
#define MTOT  8192
#define CPB   512
#define TBL   3969   // 63*63

// ---------------- scratch (device globals; no allocation) ----------------
__device__ float g_tok[MTOT * 256];
__device__ float g_qkv[MTOT * 768];
__device__ float g_att[MTOT * 256];
__device__ float g_zp [MTOT * 256];
__device__ float g_wt [4096 * 256];     // unembed weight transposed [n'][c]
__device__ float g_table[HEADS * TBL];

// ================= helpers =================
__device__ __forceinline__ uint32_t smem_u32(const void* p) {
    uint32_t a;
    asm("{ .reg .u64 t; cvta.to.shared.u64 t, %1; cvt.u32.u64 %0, t; }" : "=r"(a) : "l"(p));
    return a;
}
__device__ __forceinline__ void ldsm4(uint32_t* r, uint32_t addr) {
    asm volatile("ldmatrix.sync.aligned.m8n8.x4.shared.b16 {%0,%1,%2,%3}, [%4];"
        : "=r"(r[0]), "=r"(r[1]), "=r"(r[2]), "=r"(r[3]) : "r"(addr));
}
__device__ __forceinline__ void ldsm4t(uint32_t* r, uint32_t addr) {
    asm volatile("ldmatrix.sync.aligned.m8n8.x4.trans.shared.b16 {%0,%1,%2,%3}, [%4];"
        : "=r"(r[0]), "=r"(r[1]), "=r"(r[2]), "=r"(r[3]) : "r"(addr));
}
__device__ __forceinline__ void mma16816(float* d, const uint32_t* a, const uint32_t* b) {
    asm volatile("mma.sync.aligned.m16n8k16.row.col.f32.bf16.bf16.f32 "
        "{%0,%1,%2,%3}, {%4,%5,%6,%7}, {%8,%9}, {%0,%1,%2,%3};"
        : "+f"(d[0]), "+f"(d[1]), "+f"(d[2]), "+f"(d[3])
        : "r"(a[0]), "r"(a[1]), "r"(a[2]), "r"(a[3]), "r"(b[0]), "r"(b[1]));
}
__device__ __forceinline__ uint32_t packbf(float a, float b) {
    __nv_bfloat162 t = __halves2bfloat162(__float2bfloat16_rn(a), __float2bfloat16_rn(b));
    return *(uint32_t*)&t;
}
// pack pair into hi word + residual lo word
__device__ __forceinline__ void pack_hilo(float a, float b, uint32_t& hi, uint32_t& lo) {
    __nv_bfloat16 ha = __float2bfloat16_rn(a);
    __nv_bfloat16 hb = __float2bfloat16_rn(b);
    __nv_bfloat162 th = __halves2bfloat162(ha, hb);
    hi = *(uint32_t*)&th;
    lo = packbf(a - __bfloat162float(ha), b - __bfloat162float(hb));
}
// split 8 floats -> 4 packed hi words + 4 packed lo words, store 16B each
__device__ __forceinline__ void cvt_store8(uint16_t* hiA, uint16_t* loA, int off,
                                           float4 v0, float4 v1) {
    float f[8] = {v0.x, v0.y, v0.z, v0.w, v1.x, v1.y, v1.z, v1.w};
    uint32_t h[4], l[4];
    #pragma unroll
    for (int i = 0; i < 4; i++) pack_hilo(f[2 * i], f[2 * i + 1], h[i], l[i]);
    *(uint4*)&hiA[off] = *(uint4*)h;
    *(uint4*)&loA[off] = *(uint4*)l;
}

// ---------------- RPE MLP table ----------------
__global__ void rpe_kernel(const float* __restrict__ w1, const float* __restrict__ b1,
                           const float* __restrict__ w2) {
    __shared__ float sh[CPB];
    int e   = blockIdx.x;
    int tid = threadIdx.x;
    float rh = (float)((e / 63) - 31) * (1.0f / 31.0f);
    float rw = (float)((e % 63) - 31) * (1.0f / 31.0f);
    float r  = rh * w1[tid * 2] + rw * w1[tid * 2 + 1] + b1[tid];
    sh[tid]  = fmaxf(r, 0.0f);
    __syncthreads();
    int wid = tid >> 5, lane = tid & 31;
    if (wid < HEADS) {
        float s = 0.0f;
        for (int t = lane; t < CPB; t += 32) s += sh[t] * w2[wid * CPB + t];
        #pragma unroll
        for (int off = 16; off; off >>= 1) s += __shfl_xor_sync(0xffffffffu, s, off);
        if (lane == 0) g_table[wid * TBL + e] = s;
    }
}

// ---------------- transpose unembed weight ----------------
__global__ void wt_kernel(const float* __restrict__ w) {
    __shared__ float t[32][33];
    int n0 = blockIdx.x * 32, c0 = blockIdx.y * 32;
    int tx = threadIdx.x, ty = threadIdx.y;
    #pragma unroll
    for (int r = 0; r < 4; r++)
        t[ty + 8 * r][tx] = w[(c0 + ty + 8 * r) * 4096 + n0 + tx];
    __syncthreads();
    #pragma unroll
    for (int r = 0; r < 4; r++)
        g_wt[(n0 + ty + 8 * r) * 256 + c0 + tx] = t[tx][ty + 8 * r];
}

// ================= bf16x3 tensor-core GEMM (validated R4) =================
#define SROW 40
__global__ __launch_bounds__(256, 2)
void mma_gemm(const float* __restrict__ Ag, const float* __restrict__ Bext,
              const float* __restrict__ bias, float* __restrict__ yout,
              int asel, int csel, int K) {
    __shared__ __align__(16) uint16_t sAhi[128 * SROW];
    __shared__ __align__(16) uint16_t sAlo[128 * SROW];
    __shared__ __align__(16) uint16_t sBhi[128 * SROW];
    __shared__ __align__(16) uint16_t sBlo[128 * SROW];

    int tid = threadIdx.x, wid = tid >> 5, lane = tid & 31;
    int n0 = blockIdx.x * 128, m0 = blockIdx.y * 128;

    const float* A = asel == 1 ? g_tok : asel == 2 ? g_att : g_zp;
    const float* B = Bext ? Bext : g_wt;

    int lrow = tid >> 1, lkh = (tid & 1) * 8;
    const float* aG;
    long astep; int a2;
    if (asel == 0) {
        int m = m0 + lrow;
        int b = m >> 10, hp = (m >> 5) & 31, wp = m & 31;
        int p = lkh >> 2;
        aG = Ag + (long)b * (256 * 16384) + (hp * 4 + p) * 128 + wp * 4;
        astep = 16384; a2 = 128;
    } else {
        aG = A + (long)(m0 + lrow) * K + lkh;
        astep = 16; a2 = 4;
    }
    const float* bG = B + (long)(n0 + lrow) * K + lkh;
    int sOff = lrow * SROW + lkh;

    int wm = (wid >> 1) * 32, wn = (wid & 1) * 64;
    uint32_t baseAhi = smem_u32(sAhi), baseAlo = smem_u32(sAlo);
    uint32_t baseBhi = smem_u32(sBhi), baseBlo = smem_u32(sBlo);
    int arow = wm + (lane & 15), acol = (lane >> 4) * 8;
    uint32_t aHiAd0 = baseAhi + (arow * SROW + acol) * 2;
    uint32_t aHiAd1 = aHiAd0 + 16 * SROW * 2;
    uint32_t aLoAd0 = baseAlo + (arow * SROW + acol) * 2;
    uint32_t aLoAd1 = aLoAd0 + 16 * SROW * 2;
    int brow = wn + (lane & 7) + ((lane >> 4) << 3), bcol = lane & 8;
    uint32_t bHiAd[4], bLoAd[4];
    #pragma unroll
    for (int g = 0; g < 4; g++) {
        bHiAd[g] = baseBhi + ((brow + g * 16) * SROW + bcol) * 2;
        bLoAd[g] = baseBlo + ((brow + g * 16) * SROW + bcol) * 2;
    }

    float acc[2][8][4] = {};
    int nc = K / 16;
    float4 av0 = *(const float4*)(aG);
    float4 av1 = *(const float4*)(aG + a2);
    float4 bv0 = *(const float4*)(bG);
    float4 bv1 = *(const float4*)(bG + 4);

    for (int c = 0; c < nc; c++) {
        __syncthreads();
        cvt_store8(sAhi, sAlo, sOff, av0, av1);
        cvt_store8(sBhi, sBlo, sOff, bv0, bv1);
        __syncthreads();
        if (c + 1 < nc) {
            av0 = *(const float4*)(aG + (long)(c + 1) * astep);
            av1 = *(const float4*)(aG + (long)(c + 1) * astep + a2);
            bv0 = *(const float4*)(bG + (c + 1) * 16);
            bv1 = *(const float4*)(bG + (c + 1) * 16 + 4);
        }
        uint32_t ah[2][4], xf[2][4], bh[4][4];
        ldsm4(ah[0], aHiAd0); ldsm4(ah[1], aHiAd1);
        #pragma unroll
        for (int g = 0; g < 4; g++) ldsm4(bh[g], bHiAd[g]);
        #pragma unroll
        for (int mf = 0; mf < 2; mf++)
            #pragma unroll
            for (int g = 0; g < 4; g++) {
                mma16816(acc[mf][g * 2 + 0], ah[mf], &bh[g][0]);
                mma16816(acc[mf][g * 2 + 1], ah[mf], &bh[g][2]);
            }
        ldsm4(xf[0], aLoAd0); ldsm4(xf[1], aLoAd1);
        #pragma unroll
        for (int mf = 0; mf < 2; mf++)
            #pragma unroll
            for (int g = 0; g < 4; g++) {
                mma16816(acc[mf][g * 2 + 0], xf[mf], &bh[g][0]);
                mma16816(acc[mf][g * 2 + 1], xf[mf], &bh[g][2]);
            }
        #pragma unroll
        for (int g = 0; g < 4; g++) ldsm4(bh[g], bLoAd[g]);
        #pragma unroll
        for (int mf = 0; mf < 2; mf++)
            #pragma unroll
            for (int g = 0; g < 4; g++) {
                mma16816(acc[mf][g * 2 + 0], ah[mf], &bh[g][0]);
                mma16816(acc[mf][g * 2 + 1], ah[mf], &bh[g][2]);
            }
    }

    int r0 = m0 + wm + (lane >> 2);
    int nb = n0 + wn + (lane & 3) * 2;
    #pragma unroll
    for (int mf = 0; mf < 2; mf++) {
        int r = r0 + mf * 16;
        #pragma unroll
        for (int nf = 0; nf < 8; nf++) {
            int n = nb + nf * 8;
            float* d = acc[mf][nf];
            if (csel < 3) {
                float* C = csel == 0 ? g_tok : csel == 1 ? g_qkv : g_zp;
                int ldc = (csel == 1) ? 768 : 256;
                float b0 = __ldg(&bias[n]), b1 = __ldg(&bias[n + 1]);
                float2 lo2 = {d[0] + b0, d[1] + b1};
                float2 hi2 = {d[2] + b0, d[3] + b1};
                *(float2*)&C[(long)r * ldc + n]       = lo2;
                *(float2*)&C[(long)(r + 8) * ldc + n] = hi2;
            } else {
                int o = n >> 4, p = (n >> 2) & 3, q = n & 3;
                float bo = __ldg(&bias[o]);
                int b  = r >> 10, hp = (r >> 5) & 31, wp = r & 31;
                float2 lo2 = {d[0] + bo, d[1] + bo};
                *(float2*)&yout[((long)(b * 256 + o) * 128 + hp * 4 + p) * 128 + wp * 4 + q] = lo2;
                int r8 = r + 8;
                int b2 = r8 >> 10, hp2 = (r8 >> 5) & 31, wp2 = r8 & 31;
                float2 hi2 = {d[2] + bo, d[3] + bo};
                *(float2*)&yout[((long)(b2 * 256 + o) * 128 + hp2 * 4 + p) * 128 + wp2 * 4 + q] = hi2;
            }
        }
    }
}

// ================= tensor-core flash attention (split-P fix) =================
__global__ __launch_bounds__(256, 2)
void attn_mma_kernel() {
    __shared__ __align__(16) uint16_t sm[10240];
    uint16_t* Khi = sm;            // 64*40
    uint16_t* Klo = sm + 2560;
    uint16_t* Vhi = sm + 5120;
    uint16_t* Vlo = sm + 7680;

    int tid = threadIdx.x, w = tid >> 5, lane = tid & 31;
    int bx = blockIdx.x;
    int qs = bx & 7, bh = bx >> 3;
    int b = bh >> 3, h = bh & 7;
    int q0 = qs * 128;

    // ---- stage Q (scaled) as hi/lo bf16, then build A-fragments ----
    {
        int row = tid >> 1;
        const float* qp = &g_qkv[((b << 10) + q0 + row) * 768 + h * 32];
        #pragma unroll
        for (int it = 0; it < 2; it++) {
            int d0 = (tid & 1) * 8 + it * 16;
            float4 v0 = *(const float4*)(qp + d0);
            float4 v1 = *(const float4*)(qp + d0 + 4);
            const float S = 0.17677669529663687f;
            v0.x *= S; v0.y *= S; v0.z *= S; v0.w *= S;
            v1.x *= S; v1.y *= S; v1.z *= S; v1.w *= S;
            cvt_store8(sm, sm + 5120, row * 40 + d0, v0, v1);   // Qhi @0, Qlo @5120
        }
    }
    __syncthreads();
    uint32_t smb = smem_u32(sm);
    uint32_t qh[2][4], ql[2][4];
    {
        uint32_t qaddr = smb + ((w * 16 + (lane & 15)) * 40 + (lane >> 4) * 8) * 2;
        #pragma unroll
        for (int dc = 0; dc < 2; dc++) {
            ldsm4(qh[dc], qaddr + dc * 32);
            ldsm4(ql[dc], qaddr + 10240 + dc * 32);
        }
    }

    uint32_t kaddr = smb + (((lane & 7) + ((lane >> 4) << 3)) * 40 + (lane & 8)) * 2;
    uint32_t vaddr = smb + 10240 + ((lane & 15) * 40 + (lane >> 4) * 8) * 2;

    int nq0 = q0 + w * 16 + (lane >> 2);
    int nq1 = nq0 + 8;
    int bi0 = ((nq0 >> 5) + 31) * 63 + (nq0 & 31) + 31;
    int bi1 = ((nq1 >> 5) + 31) * 63 + (nq1 & 31) + 31;
    const float* tab = g_table + h * TBL;

    float m0r = -1e30f, m1r = -1e30f, l0 = 0.0f, l1 = 0.0f;
    float O[4][4] = {};

    for (int t = 0; t < 16; t++) {
        __syncthreads();
        {   // load K/V tile (64 rows x 32 d), convert to hi/lo
            int row = tid >> 2, dg = (tid & 3) * 8;
            const float* rp = &g_qkv[((b << 10) + t * 64 + row) * 768 + h * 32 + dg];
            float4 ka = *(const float4*)(rp + 256);
            float4 kb = *(const float4*)(rp + 260);
            float4 va = *(const float4*)(rp + 512);
            float4 vb = *(const float4*)(rp + 516);
            cvt_store8(Khi, Klo, row * 40 + dg, ka, kb);
            cvt_store8(Vhi, Vlo, row * 40 + dg, va, vb);
        }
        __syncthreads();

        // ---- S = QK^T (16q x 64k per warp), 3-product bf16 split ----
        float sc[8][4] = {};
        #pragma unroll
        for (int dc = 0; dc < 2; dc++) {
            #pragma unroll
            for (int nfp = 0; nfp < 4; nfp++) {
                uint32_t off = (nfp * 640 + dc * 16) * 2;
                uint32_t bh4[4];
                ldsm4(bh4, kaddr + off);
                mma16816(sc[2 * nfp],     qh[dc], &bh4[0]);
                mma16816(sc[2 * nfp + 1], qh[dc], &bh4[2]);
                mma16816(sc[2 * nfp],     ql[dc], &bh4[0]);
                mma16816(sc[2 * nfp + 1], ql[dc], &bh4[2]);
                ldsm4(bh4, kaddr + 5120 + off);
                mma16816(sc[2 * nfp],     qh[dc], &bh4[0]);
                mma16816(sc[2 * nfp + 1], qh[dc], &bh4[2]);
            }
        }

        // ---- bias add ----
        int tb = t * 126;
        #pragma unroll
        for (int nf = 0; nf < 8; nf++) {
            int cb = (nf >> 2) * 63 + (nf & 3) * 8 + (lane & 3) * 2;
            sc[nf][0] += __ldg(&tab[bi0 - tb - cb]);
            sc[nf][1] += __ldg(&tab[bi0 - tb - cb - 1]);
            sc[nf][2] += __ldg(&tab[bi1 - tb - cb]);
            sc[nf][3] += __ldg(&tab[bi1 - tb - cb - 1]);
        }

        // ---- online softmax (rows owned by quad); p written back into sc ----
        float mx0 = -1e30f, mx1 = -1e30f;
        #pragma unroll
        for (int nf = 0; nf < 8; nf++) {
            mx0 = fmaxf(mx0, fmaxf(sc[nf][0], sc[nf][1]));
            mx1 = fmaxf(mx1, fmaxf(sc[nf][2], sc[nf][3]));
        }
        #pragma unroll
        for (int off = 1; off < 4; off <<= 1) {
            mx0 = fmaxf(mx0, __shfl_xor_sync(0xffffffffu, mx0, off));
            mx1 = fmaxf(mx1, __shfl_xor_sync(0xffffffffu, mx1, off));
        }
        float mn0 = fmaxf(m0r, mx0), mn1 = fmaxf(m1r, mx1);
        float s0 = __expf(m0r - mn0), s1 = __expf(m1r - mn1);
        m0r = mn0; m1r = mn1;

        float ps0 = 0.0f, ps1 = 0.0f;
        #pragma unroll
        for (int nf = 0; nf < 8; nf++) {
            float p0 = __expf(sc[nf][0] - mn0);
            float p1 = __expf(sc[nf][1] - mn0);
            float p2 = __expf(sc[nf][2] - mn1);
            float p3 = __expf(sc[nf][3] - mn1);
            ps0 += p0 + p1; ps1 += p2 + p3;
            sc[nf][0] = p0; sc[nf][1] = p1; sc[nf][2] = p2; sc[nf][3] = p3;
        }
        #pragma unroll
        for (int off = 1; off < 4; off <<= 1) {
            ps0 += __shfl_xor_sync(0xffffffffu, ps0, off);
            ps1 += __shfl_xor_sync(0xffffffffu, ps1, off);
        }
        l0 = l0 * s0 + ps0;
        l1 = l1 * s1 + ps1;
        #pragma unroll
        for (int nf = 0; nf < 4; nf++) {
            O[nf][0] *= s0; O[nf][1] *= s0;
            O[nf][2] *= s1; O[nf][3] *= s1;
        }

        // ---- O += Phi*(Vhi+Vlo) + Plo*Vhi ----
        #pragma unroll
        for (int kc = 0; kc < 4; kc++) {
            uint32_t ph[4], pl[4];
            pack_hilo(sc[2 * kc][0],     sc[2 * kc][1],     ph[0], pl[0]);
            pack_hilo(sc[2 * kc][2],     sc[2 * kc][3],     ph[1], pl[1]);
            pack_hilo(sc[2 * kc + 1][0], sc[2 * kc + 1][1], ph[2], pl[2]);
            pack_hilo(sc[2 * kc + 1][2], sc[2 * kc + 1][3], ph[3], pl[3]);
            #pragma unroll
            for (int dfp = 0; dfp < 2; dfp++) {
                uint32_t off = (kc * 640 + dfp * 16) * 2;
                uint32_t vb4[4];
                ldsm4t(vb4, vaddr + off);
                mma16816(O[2 * dfp],     ph, &vb4[0]);
                mma16816(O[2 * dfp + 1], ph, &vb4[2]);
                mma16816(O[2 * dfp],     pl, &vb4[0]);
                mma16816(O[2 * dfp + 1], pl, &vb4[2]);
                ldsm4t(vb4, vaddr + 5120 + off);
                mma16816(O[2 * dfp],     ph, &vb4[0]);
                mma16816(O[2 * dfp + 1], ph, &vb4[2]);
            }
        }
    }

    // ---- epilogue ----
    float i0 = 1.0f / l0, i1 = 1.0f / l1;
    #pragma unroll
    for (int nf = 0; nf < 4; nf++) {
        int d = h * 32 + nf * 8 + (lane & 3) * 2;
        float2 o0 = {O[nf][0] * i0, O[nf][1] * i0};
        float2 o1 = {O[nf][2] * i1, O[nf][3] * i1};
        *(float2*)&g_att[((b << 10) + nq0) * 256 + d] = o0;
        *(float2*)&g_att[((b << 10) + nq1) * 256 + d] = o1;
    }
}

// ---------------- launch ----------------
extern "C" void kernel_launch(void* const* d_in, const int* in_sizes, int n_in,
                              void* d_out, int out_size) {
    const float* x         = (const float*)d_in[0];
    const float* w_embed   = (const float*)d_in[1];
    const float* b_embed   = (const float*)d_in[2];
    const float* cpb_w1    = (const float*)d_in[3];
    const float* cpb_b1    = (const float*)d_in[4];
    const float* cpb_w2    = (const float*)d_in[5];
    const float* w_qkv     = (const float*)d_in[6];
    const float* b_qkv     = (const float*)d_in[7];
    const float* w_proj    = (const float*)d_in[8];
    const float* b_proj    = (const float*)d_in[9];
    const float* w_unembed = (const float*)d_in[10];
    const float* b_unembed = (const float*)d_in[11];
    float* y = (float*)d_out;

    rpe_kernel<<<TBL, CPB>>>(cpb_w1, cpb_b1, cpb_w2);
    wt_kernel <<<dim3(128, 8), dim3(32, 8)>>>(w_unembed);
    mma_gemm<<<dim3(2, 64), 256>>>(x, w_embed, b_embed, nullptr, 0, 0, 4096);
    mma_gemm<<<dim3(6, 64), 256>>>(nullptr, w_qkv, b_qkv, nullptr, 1, 1, 256);
    attn_mma_kernel<<<512, 256>>>();
    mma_gemm<<<dim3(2, 64), 256>>>(nullptr, w_proj, b_proj, nullptr, 2, 2, 256);
    mma_gemm<<<dim3(32, 64), 256>>>(nullptr, nullptr, b_unembed, y, 3, 3, 256);
}

// round 7
// speedup vs baseline: 6.8675x; 1.0907x over previous
#include <cuda_runtime.h>
#include <cuda_bf16.h>
#include <stdint.h>

#define HEADS 8
#define MTOT  8192
#define CPB   512
#define TBL   3969   // 63*63

// ---------------- scratch (device globals; no allocation) ----------------
__device__ float g_tok[MTOT * 256];
__device__ float g_qkv[MTOT * 768];
__device__ float g_att[MTOT * 256];
__device__ float g_zp [MTOT * 256];
__device__ float g_wt [4096 * 256];     // unembed weight transposed [n'][c]
__device__ float g_table[HEADS * TBL];

// ================= helpers =================
__device__ __forceinline__ uint32_t smem_u32(const void* p) {
    uint32_t a;
    asm("{ .reg .u64 t; cvta.to.shared.u64 t, %1; cvt.u32.u64 %0, t; }" : "=r"(a) : "l"(p));
    return a;
}
__device__ __forceinline__ void ldsm4(uint32_t* r, uint32_t addr) {
    asm volatile("ldmatrix.sync.aligned.m8n8.x4.shared.b16 {%0,%1,%2,%3}, [%4];"
        : "=r"(r[0]), "=r"(r[1]), "=r"(r[2]), "=r"(r[3]) : "r"(addr));
}
__device__ __forceinline__ void ldsm4t(uint32_t* r, uint32_t addr) {
    asm volatile("ldmatrix.sync.aligned.m8n8.x4.trans.shared.b16 {%0,%1,%2,%3}, [%4];"
        : "=r"(r[0]), "=r"(r[1]), "=r"(r[2]), "=r"(r[3]) : "r"(addr));
}
__device__ __forceinline__ void mma16816(float* d, const uint32_t* a, const uint32_t* b) {
    asm volatile("mma.sync.aligned.m16n8k16.row.col.f32.bf16.bf16.f32 "
        "{%0,%1,%2,%3}, {%4,%5,%6,%7}, {%8,%9}, {%0,%1,%2,%3};"
        : "+f"(d[0]), "+f"(d[1]), "+f"(d[2]), "+f"(d[3])
        : "r"(a[0]), "r"(a[1]), "r"(a[2]), "r"(a[3]), "r"(b[0]), "r"(b[1]));
}
__device__ __forceinline__ uint32_t packbf(float a, float b) {
    __nv_bfloat162 t = __halves2bfloat162(__float2bfloat16_rn(a), __float2bfloat16_rn(b));
    return *(uint32_t*)&t;
}
__device__ __forceinline__ void pack_hilo(float a, float b, uint32_t& hi, uint32_t& lo) {
    __nv_bfloat16 ha = __float2bfloat16_rn(a);
    __nv_bfloat16 hb = __float2bfloat16_rn(b);
    __nv_bfloat162 th = __halves2bfloat162(ha, hb);
    hi = *(uint32_t*)&th;
    lo = packbf(a - __bfloat162float(ha), b - __bfloat162float(hb));
}
__device__ __forceinline__ void cvt_store8(uint16_t* hiA, uint16_t* loA, int off,
                                           float4 v0, float4 v1) {
    float f[8] = {v0.x, v0.y, v0.z, v0.w, v1.x, v1.y, v1.z, v1.w};
    uint32_t h[4], l[4];
    #pragma unroll
    for (int i = 0; i < 4; i++) pack_hilo(f[2 * i], f[2 * i + 1], h[i], l[i]);
    *(uint4*)&hiA[off] = *(uint4*)h;
    *(uint4*)&loA[off] = *(uint4*)l;
}
__device__ __forceinline__ void cvt_store4(uint16_t* hiA, uint16_t* loA, int off, float4 v) {
    uint32_t h[2], l[2];
    pack_hilo(v.x, v.y, h[0], l[0]);
    pack_hilo(v.z, v.w, h[1], l[1]);
    *(uint2*)&hiA[off] = *(uint2*)h;
    *(uint2*)&loA[off] = *(uint2*)l;
}

// ---------------- RPE MLP table ----------------
__global__ void rpe_kernel(const float* __restrict__ w1, const float* __restrict__ b1,
                           const float* __restrict__ w2) {
    __shared__ float sh[CPB];
    int e   = blockIdx.x;
    int tid = threadIdx.x;
    float rh = (float)((e / 63) - 31) * (1.0f / 31.0f);
    float rw = (float)((e % 63) - 31) * (1.0f / 31.0f);
    float r  = rh * w1[tid * 2] + rw * w1[tid * 2 + 1] + b1[tid];
    sh[tid]  = fmaxf(r, 0.0f);
    __syncthreads();
    int wid = tid >> 5, lane = tid & 31;
    if (wid < HEADS) {
        float s = 0.0f;
        for (int t = lane; t < CPB; t += 32) s += sh[t] * w2[wid * CPB + t];
        #pragma unroll
        for (int off = 16; off; off >>= 1) s += __shfl_xor_sync(0xffffffffu, s, off);
        if (lane == 0) g_table[wid * TBL + e] = s;
    }
}

// ---------------- transpose unembed weight ----------------
__global__ void wt_kernel(const float* __restrict__ w) {
    __shared__ float t[32][33];
    int n0 = blockIdx.x * 32, c0 = blockIdx.y * 32;
    int tx = threadIdx.x, ty = threadIdx.y;
    #pragma unroll
    for (int r = 0; r < 4; r++)
        t[ty + 8 * r][tx] = w[(c0 + ty + 8 * r) * 4096 + n0 + tx];
    __syncthreads();
    #pragma unroll
    for (int r = 0; r < 4; r++)
        g_wt[(n0 + ty + 8 * r) * 256 + c0 + tx] = t[tx][ty + 8 * r];
}

// ================= bf16x3 tensor-core GEMM, double-buffered, NT-templated =================
// C[M=8192, NT*gridX] = A[M,K] * B[N,K]^T + bias
#define SR 24   // smem row stride in bf16 (16 data + 8 pad); conflict-free ldmatrix
template<int NT>
__global__ __launch_bounds__(256, 2)
void mma_gemm(const float* __restrict__ Ag, const float* __restrict__ Bext,
              const float* __restrict__ bias, float* __restrict__ yout,
              int asel, int csel, int K) {
    constexpr int NGRP = NT / 32;                 // B 16-row frag groups per warp = 2*NGRP
    __shared__ __align__(16) uint16_t sAhi[2 * 128 * SR];
    __shared__ __align__(16) uint16_t sAlo[2 * 128 * SR];
    __shared__ __align__(16) uint16_t sBhi[2 * NT * SR];
    __shared__ __align__(16) uint16_t sBlo[2 * NT * SR];

    int tid = threadIdx.x, wid = tid >> 5, lane = tid & 31;
    int n0 = blockIdx.x * NT, m0 = blockIdx.y * 128;

    const float* A = asel == 1 ? g_tok : asel == 2 ? g_att : g_zp;
    const float* B = Bext ? Bext : g_wt;

    // ---- A load geometry: row tid>>1, k-half (tid&1)*8 ----
    int lrow = tid >> 1, lkh = (tid & 1) * 8;
    const float* aG;
    long astep; int a2;
    if (asel == 0) {
        int m = m0 + lrow;
        int b = m >> 10, hp = (m >> 5) & 31, wp = m & 31;
        int p = lkh >> 2;
        aG = Ag + (long)b * (256 * 16384) + (hp * 4 + p) * 128 + wp * 4;
        astep = 16384; a2 = 128;
    } else {
        aG = A + (long)(m0 + lrow) * K + lkh;
        astep = 16; a2 = 4;
    }
    int aoff = lrow * SR + lkh;

    // ---- B load geometry ----
    const float* bG;
    int boff;
    if (NT == 128) { bG = B + (long)(n0 + lrow) * K + lkh;          boff = aoff; }
    else           { bG = B + (long)(n0 + (tid >> 2)) * K + (tid & 3) * 4;
                     boff = (tid >> 2) * SR + (tid & 3) * 4; }

    // ---- fragment addresses (buffer 0) ----
    int wm = (wid >> 1) * 32, wn = (wid & 1) * (NT / 2);
    uint32_t aHiB = smem_u32(sAhi), aLoB = smem_u32(sAlo);
    uint32_t bHiB = smem_u32(sBhi), bLoB = smem_u32(sBlo);
    constexpr uint32_t ABUF = 128 * SR * 2, BBUF = NT * SR * 2;
    uint32_t aOff0 = ((wm + (lane & 15)) * SR + (lane >> 4) * 8) * 2;
    uint32_t aOff1 = aOff0 + 16 * SR * 2;
    int brow = wn + (lane & 7) + ((lane >> 4) << 3), bcol = lane & 8;
    uint32_t bOff[NGRP];
    #pragma unroll
    for (int g = 0; g < NGRP; g++) bOff[g] = ((brow + g * 16) * SR + bcol) * 2;

    float acc[2][2 * NGRP][4] = {};
    int nc = K / 16;

    // prefetch chunk 0, store to buffer 0, prefetch chunk 1
    float4 av0 = *(const float4*)(aG);
    float4 av1 = *(const float4*)(aG + a2);
    float4 bv0, bv1;
    if (NT == 128) { bv0 = *(const float4*)(bG); bv1 = *(const float4*)(bG + 4); }
    else           { bv0 = *(const float4*)(bG); }
    cvt_store8(sAhi, sAlo, aoff, av0, av1);
    if (NT == 128) cvt_store8(sBhi, sBlo, boff, bv0, bv1);
    else           cvt_store4(sBhi, sBlo, boff, bv0);
    av0 = *(const float4*)(aG + astep);
    av1 = *(const float4*)(aG + astep + a2);
    if (NT == 128) { bv0 = *(const float4*)(bG + 16); bv1 = *(const float4*)(bG + 20); }
    else           { bv0 = *(const float4*)(bG + 16); }

    for (int c = 0; c < nc; c++) {
        __syncthreads();
        uint32_t pa = (c & 1) * ABUF, pb = (c & 1) * BBUF;
        uint32_t ah[2][4], al[2][4], bh4[NGRP][4];
        ldsm4(ah[0], aHiB + pa + aOff0);
        ldsm4(ah[1], aHiB + pa + aOff1);
        ldsm4(al[0], aLoB + pa + aOff0);
        ldsm4(al[1], aLoB + pa + aOff1);
        #pragma unroll
        for (int g = 0; g < NGRP; g++) ldsm4(bh4[g], bHiB + pb + bOff[g]);

        // store chunk c+1 into alternate buffer; prefetch chunk c+2
        if (c + 1 < nc) {
            int b1 = (c + 1) & 1;
            cvt_store8(sAhi + b1 * (128 * SR), sAlo + b1 * (128 * SR), aoff, av0, av1);
            if (NT == 128) cvt_store8(sBhi + b1 * (NT * SR), sBlo + b1 * (NT * SR), boff, bv0, bv1);
            else           cvt_store4(sBhi + b1 * (NT * SR), sBlo + b1 * (NT * SR), boff, bv0);
            if (c + 2 < nc) {
                av0 = *(const float4*)(aG + (long)(c + 2) * astep);
                av1 = *(const float4*)(aG + (long)(c + 2) * astep + a2);
                if (NT == 128) { bv0 = *(const float4*)(bG + (c + 2) * 16);
                                 bv1 = *(const float4*)(bG + (c + 2) * 16 + 4); }
                else           { bv0 = *(const float4*)(bG + (c + 2) * 16); }
            }
        }

        // pass1: Ahi * Bhi ; pass2: Alo * Bhi
        #pragma unroll
        for (int mf = 0; mf < 2; mf++)
            #pragma unroll
            for (int g = 0; g < NGRP; g++) {
                mma16816(acc[mf][g * 2 + 0], ah[mf], &bh4[g][0]);
                mma16816(acc[mf][g * 2 + 1], ah[mf], &bh4[g][2]);
            }
        #pragma unroll
        for (int mf = 0; mf < 2; mf++)
            #pragma unroll
            for (int g = 0; g < NGRP; g++) {
                mma16816(acc[mf][g * 2 + 0], al[mf], &bh4[g][0]);
                mma16816(acc[mf][g * 2 + 1], al[mf], &bh4[g][2]);
            }
        // pass3: Ahi * Blo
        #pragma unroll
        for (int g = 0; g < NGRP; g++) ldsm4(bh4[g], bLoB + pb + bOff[g]);
        #pragma unroll
        for (int mf = 0; mf < 2; mf++)
            #pragma unroll
            for (int g = 0; g < NGRP; g++) {
                mma16816(acc[mf][g * 2 + 0], ah[mf], &bh4[g][0]);
                mma16816(acc[mf][g * 2 + 1], ah[mf], &bh4[g][2]);
            }
    }

    // ---- epilogue ----
    int r0 = m0 + wm + (lane >> 2);
    int nb = n0 + wn + (lane & 3) * 2;
    #pragma unroll
    for (int mf = 0; mf < 2; mf++) {
        int r = r0 + mf * 16;
        #pragma unroll
        for (int nf = 0; nf < 2 * NGRP; nf++) {
            int n = nb + nf * 8;
            float* d = acc[mf][nf];
            if (csel < 3) {
                float* C = csel == 0 ? g_tok : csel == 1 ? g_qkv : g_zp;
                int ldc = (csel == 1) ? 768 : 256;
                float b0 = __ldg(&bias[n]), b1 = __ldg(&bias[n + 1]);
                float2 lo2 = {d[0] + b0, d[1] + b1};
                float2 hi2 = {d[2] + b0, d[3] + b1};
                *(float2*)&C[(long)r * ldc + n]       = lo2;
                *(float2*)&C[(long)(r + 8) * ldc + n] = hi2;
            } else {
                int o = n >> 4, p = (n >> 2) & 3, q = n & 3;
                float bo = __ldg(&bias[o]);
                int b  = r >> 10, hp = (r >> 5) & 31, wp = r & 31;
                float2 lo2 = {d[0] + bo, d[1] + bo};
                *(float2*)&yout[((long)(b * 256 + o) * 128 + hp * 4 + p) * 128 + wp * 4 + q] = lo2;
                int r8 = r + 8;
                int b2 = r8 >> 10, hp2 = (r8 >> 5) & 31, wp2 = r8 & 31;
                float2 hi2 = {d[2] + bo, d[3] + bo};
                *(float2*)&yout[((long)(b2 * 256 + o) * 128 + hp2 * 4 + p) * 128 + wp2 * 4 + q] = hi2;
            }
        }
    }
}

// ================= tensor-core flash attention (validated R6, unchanged) =================
__global__ __launch_bounds__(256, 2)
void attn_mma_kernel() {
    __shared__ __align__(16) uint16_t sm[10240];
    uint16_t* Khi = sm;            // 64*40
    uint16_t* Klo = sm + 2560;
    uint16_t* Vhi = sm + 5120;
    uint16_t* Vlo = sm + 7680;

    int tid = threadIdx.x, w = tid >> 5, lane = tid & 31;
    int bx = blockIdx.x;
    int qs = bx & 7, bh = bx >> 3;
    int b = bh >> 3, h = bh & 7;
    int q0 = qs * 128;

    {
        int row = tid >> 1;
        const float* qp = &g_qkv[((b << 10) + q0 + row) * 768 + h * 32];
        #pragma unroll
        for (int it = 0; it < 2; it++) {
            int d0 = (tid & 1) * 8 + it * 16;
            float4 v0 = *(const float4*)(qp + d0);
            float4 v1 = *(const float4*)(qp + d0 + 4);
            const float S = 0.17677669529663687f;
            v0.x *= S; v0.y *= S; v0.z *= S; v0.w *= S;
            v1.x *= S; v1.y *= S; v1.z *= S; v1.w *= S;
            cvt_store8(sm, sm + 5120, row * 40 + d0, v0, v1);
        }
    }
    __syncthreads();
    uint32_t smb = smem_u32(sm);
    uint32_t qh[2][4], ql[2][4];
    {
        uint32_t qaddr = smb + ((w * 16 + (lane & 15)) * 40 + (lane >> 4) * 8) * 2;
        #pragma unroll
        for (int dc = 0; dc < 2; dc++) {
            ldsm4(qh[dc], qaddr + dc * 32);
            ldsm4(ql[dc], qaddr + 10240 + dc * 32);
        }
    }

    uint32_t kaddr = smb + (((lane & 7) + ((lane >> 4) << 3)) * 40 + (lane & 8)) * 2;
    uint32_t vaddr = smb + 10240 + ((lane & 15) * 40 + (lane >> 4) * 8) * 2;

    int nq0 = q0 + w * 16 + (lane >> 2);
    int nq1 = nq0 + 8;
    int bi0 = ((nq0 >> 5) + 31) * 63 + (nq0 & 31) + 31;
    int bi1 = ((nq1 >> 5) + 31) * 63 + (nq1 & 31) + 31;
    const float* tab = g_table + h * TBL;

    float m0r = -1e30f, m1r = -1e30f, l0 = 0.0f, l1 = 0.0f;
    float O[4][4] = {};

    for (int t = 0; t < 16; t++) {
        __syncthreads();
        {
            int row = tid >> 2, dg = (tid & 3) * 8;
            const float* rp = &g_qkv[((b << 10) + t * 64 + row) * 768 + h * 32 + dg];
            float4 ka = *(const float4*)(rp + 256);
            float4 kb = *(const float4*)(rp + 260);
            float4 va = *(const float4*)(rp + 512);
            float4 vb = *(const float4*)(rp + 516);
            cvt_store8(Khi, Klo, row * 40 + dg, ka, kb);
            cvt_store8(Vhi, Vlo, row * 40 + dg, va, vb);
        }
        __syncthreads();

        float sc[8][4] = {};
        #pragma unroll
        for (int dc = 0; dc < 2; dc++) {
            #pragma unroll
            for (int nfp = 0; nfp < 4; nfp++) {
                uint32_t off = (nfp * 640 + dc * 16) * 2;
                uint32_t bh4[4];
                ldsm4(bh4, kaddr + off);
                mma16816(sc[2 * nfp],     qh[dc], &bh4[0]);
                mma16816(sc[2 * nfp + 1], qh[dc], &bh4[2]);
                mma16816(sc[2 * nfp],     ql[dc], &bh4[0]);
                mma16816(sc[2 * nfp + 1], ql[dc], &bh4[2]);
                ldsm4(bh4, kaddr + 5120 + off);
                mma16816(sc[2 * nfp],     qh[dc], &bh4[0]);
                mma16816(sc[2 * nfp + 1], qh[dc], &bh4[2]);
            }
        }

        int tb = t * 126;
        #pragma unroll
        for (int nf = 0; nf < 8; nf++) {
            int cb = (nf >> 2) * 63 + (nf & 3) * 8 + (lane & 3) * 2;
            sc[nf][0] += __ldg(&tab[bi0 - tb - cb]);
            sc[nf][1] += __ldg(&tab[bi0 - tb - cb - 1]);
            sc[nf][2] += __ldg(&tab[bi1 - tb - cb]);
            sc[nf][3] += __ldg(&tab[bi1 - tb - cb - 1]);
        }

        float mx0 = -1e30f, mx1 = -1e30f;
        #pragma unroll
        for (int nf = 0; nf < 8; nf++) {
            mx0 = fmaxf(mx0, fmaxf(sc[nf][0], sc[nf][1]));
            mx1 = fmaxf(mx1, fmaxf(sc[nf][2], sc[nf][3]));
        }
        #pragma unroll
        for (int off = 1; off < 4; off <<= 1) {
            mx0 = fmaxf(mx0, __shfl_xor_sync(0xffffffffu, mx0, off));
            mx1 = fmaxf(mx1, __shfl_xor_sync(0xffffffffu, mx1, off));
        }
        float mn0 = fmaxf(m0r, mx0), mn1 = fmaxf(m1r, mx1);
        float s0 = __expf(m0r - mn0), s1 = __expf(m1r - mn1);
        m0r = mn0; m1r = mn1;

        float ps0 = 0.0f, ps1 = 0.0f;
        #pragma unroll
        for (int nf = 0; nf < 8; nf++) {
            float p0 = __expf(sc[nf][0] - mn0);
            float p1 = __expf(sc[nf][1] - mn0);
            float p2 = __expf(sc[nf][2] - mn1);
            float p3 = __expf(sc[nf][3] - mn1);
            ps0 += p0 + p1; ps1 += p2 + p3;
            sc[nf][0] = p0; sc[nf][1] = p1; sc[nf][2] = p2; sc[nf][3] = p3;
        }
        #pragma unroll
        for (int off = 1; off < 4; off <<= 1) {
            ps0 += __shfl_xor_sync(0xffffffffu, ps0, off);
            ps1 += __shfl_xor_sync(0xffffffffu, ps1, off);
        }
        l0 = l0 * s0 + ps0;
        l1 = l1 * s1 + ps1;
        #pragma unroll
        for (int nf = 0; nf < 4; nf++) {
            O[nf][0] *= s0; O[nf][1] *= s0;
            O[nf][2] *= s1; O[nf][3] *= s1;
        }

        #pragma unroll
        for (int kc = 0; kc < 4; kc++) {
            uint32_t ph[4], pl[4];
            pack_hilo(sc[2 * kc][0],     sc[2 * kc][1],     ph[0], pl[0]);
            pack_hilo(sc[2 * kc][2],     sc[2 * kc][3],     ph[1], pl[1]);
            pack_hilo(sc[2 * kc + 1][0], sc[2 * kc + 1][1], ph[2], pl[2]);
            pack_hilo(sc[2 * kc + 1][2], sc[2 * kc + 1][3], ph[3], pl[3]);
            #pragma unroll
            for (int dfp = 0; dfp < 2; dfp++) {
                uint32_t off = (kc * 640 + dfp * 16) * 2;
                uint32_t vb4[4];
                ldsm4t(vb4, vaddr + off);
                mma16816(O[2 * dfp],     ph, &vb4[0]);
                mma16816(O[2 * dfp + 1], ph, &vb4[2]);
                mma16816(O[2 * dfp],     pl, &vb4[0]);
                mma16816(O[2 * dfp + 1], pl, &vb4[2]);
                ldsm4t(vb4, vaddr + 5120 + off);
                mma16816(O[2 * dfp],     ph, &vb4[0]);
                mma16816(O[2 * dfp + 1], ph, &vb4[2]);
            }
        }
    }

    float i0 = 1.0f / l0, i1 = 1.0f / l1;
    #pragma unroll
    for (int nf = 0; nf < 4; nf++) {
        int d = h * 32 + nf * 8 + (lane & 3) * 2;
        float2 o0 = {O[nf][0] * i0, O[nf][1] * i0};
        float2 o1 = {O[nf][2] * i1, O[nf][3] * i1};
        *(float2*)&g_att[((b << 10) + nq0) * 256 + d] = o0;
        *(float2*)&g_att[((b << 10) + nq1) * 256 + d] = o1;
    }
}

// ---------------- launch ----------------
extern "C" void kernel_launch(void* const* d_in, const int* in_sizes, int n_in,
                              void* d_out, int out_size) {
    const float* x         = (const float*)d_in[0];
    const float* w_embed   = (const float*)d_in[1];
    const float* b_embed   = (const float*)d_in[2];
    const float* cpb_w1    = (const float*)d_in[3];
    const float* cpb_b1    = (const float*)d_in[4];
    const float* cpb_w2    = (const float*)d_in[5];
    const float* w_qkv     = (const float*)d_in[6];
    const float* b_qkv     = (const float*)d_in[7];
    const float* w_proj    = (const float*)d_in[8];
    const float* b_proj    = (const float*)d_in[9];
    const float* w_unembed = (const float*)d_in[10];
    const float* b_unembed = (const float*)d_in[11];
    float* y = (float*)d_out;

    rpe_kernel<<<TBL, CPB>>>(cpb_w1, cpb_b1, cpb_w2);
    wt_kernel <<<dim3(128, 8), dim3(32, 8)>>>(w_unembed);
    // embed: NT=64 -> 256 CTAs (one resident wave on 148 SMs x 2)
    mma_gemm<64> <<<dim3(4, 64),  256>>>(x, w_embed, b_embed, nullptr, 0, 0, 4096);
    // qkv: NT=128 -> 384 CTAs
    mma_gemm<128><<<dim3(6, 64),  256>>>(nullptr, w_qkv, b_qkv, nullptr, 1, 1, 256);
    attn_mma_kernel<<<512, 256>>>();
    // proj: NT=64 -> 256 CTAs
    mma_gemm<64> <<<dim3(4, 64),  256>>>(nullptr, w_proj, b_proj, nullptr, 2, 2, 256);
    // unembed: NT=128 -> 2048 CTAs
    mma_gemm<128><<<dim3(32, 64), 256>>>(nullptr, nullptr, b_unembed, y, 3, 3, 256);
}